// round 1
// baseline (speedup 1.0000x reference)
#include <cuda_runtime.h>

// ---------------- problem constants (fixed shapes from setup_inputs) --------
#define Bb   320      // x batch
#define Cc   512      // channels
#define Tt   32       // time (== W)
#define BSz  32       // deform batch (Bb/10)
#define Hh   10
#define Ww   32
#define Gg   16       // groups
#define Cg   32       // channels per group
#define KKn  9        // 3x3 taps
#define Kd   4608     // Gg*KKn*Cg  (GEMM reduction dim)
#define Mm   10240    // BSz*Hh*Ww  (GEMM rows)
#define Nn   512      // output channels (GEMM cols)

// ---------------- device scratch (no allocations allowed) -------------------
__device__ float g_mean[Cc];
__device__ float g_istd[Cc];
__device__ float g_Xg[BSz * Gg * Hh * Ww * Cg];      // normalized, group-major, c contiguous
__device__ float g_col[(long long)Mm * Kd];          // im2col of deformable samples (189 MB)
__device__ float g_Bt[(long long)Kd * Nn];           // weight permuted to [kd][o]

// ---------------- 1) BN statistics per channel ------------------------------
__global__ void bn_stats_kernel(const float* __restrict__ x) {
    int c = blockIdx.x;
    float s = 0.f, s2 = 0.f;
    for (int i = threadIdx.x; i < Bb * Tt; i += blockDim.x) {
        int b = i >> 5;       // Tt == 32
        int t = i & 31;
        float v = x[(b * Cc + c) * Tt + t];
        s += v; s2 += v * v;
    }
    __shared__ float sh[256], sh2[256];
    sh[threadIdx.x] = s; sh2[threadIdx.x] = s2;
    __syncthreads();
    for (int o = 128; o > 0; o >>= 1) {
        if (threadIdx.x < o) {
            sh[threadIdx.x]  += sh[threadIdx.x + o];
            sh2[threadIdx.x] += sh2[threadIdx.x + o];
        }
        __syncthreads();
    }
    if (threadIdx.x == 0) {
        const float inv_n = 1.0f / (float)(Bb * Tt);
        float mean = sh[0] * inv_n;
        float var  = sh2[0] * inv_n - mean * mean;
        g_mean[c] = mean;
        g_istd[c] = rsqrtf(var + 1e-5f);
    }
}

// ---------------- 2) normalize + relayout to (bs,g,h,w,c) -------------------
__global__ void build_xg_kernel(const float* __restrict__ x,
                                const float* __restrict__ gamma,
                                const float* __restrict__ beta) {
    int idx = blockIdx.x * blockDim.x + threadIdx.x;
    if (idx >= BSz * Gg * Hh * Ww * Cg) return;
    int c  = idx & 31;
    int w  = (idx >> 5) & 31;
    int h  = (idx >> 10) % Hh;
    int g  = (idx / (Cg * Ww * Hh)) % Gg;
    int bs = idx / (Cg * Ww * Hh * Gg);
    int ch = g * Cg + c;
    float v = x[((bs * 10 + h) * Cc + ch) * Tt + w];
    g_Xg[idx] = (v - g_mean[ch]) * g_istd[ch] * gamma[ch] + beta[ch];
}

// ---------------- 3) permute weight to [kd][o] ------------------------------
__global__ void wtrans_kernel(const float* __restrict__ weight) {
    int idx = blockIdx.x * blockDim.x + threadIdx.x;
    if (idx >= Kd * Nn) return;
    int o  = idx & (Nn - 1);
    int kd = idx >> 9;
    int g  = kd / (KKn * Cg);
    int r  = kd % (KKn * Cg);
    int kk = r >> 5;
    int c  = r & 31;
    g_Bt[(long long)kd * Nn + o] = weight[(long long)o * Kd + (g * Cg + c) * KKn + kk];
}

// ---------------- 4) deformable bilinear sampling -> col --------------------
// One warp handles one (b,g,h,w,kk); lane == channel within group.
__global__ void im2col_kernel(const float* __restrict__ offset,
                              const float* __restrict__ mask) {
    int warp = (blockIdx.x * blockDim.x + threadIdx.x) >> 5;
    int lane = threadIdx.x & 31;
    if (warp >= BSz * Gg * Hh * Ww * KKn) return;

    int kk = warp % 9;
    int w  = (warp / 9) % 32;
    int h  = (warp / 288) % 10;
    int g  = (warp / 2880) % 16;
    int b  = warp / 46080;

    int ky = kk / 3, kx = kk % 3;
    int hw = h * Ww + w;

    // offset channel layout: (g*9+kk)*2 + {0:dy,1:dx}; plane stride H*W = 320
    int oc = (g * 9 + kk) * 2;
    float dy = offset[((long long)b * 288 + oc)     * 320 + hw];
    float dx = offset[((long long)b * 288 + oc + 1) * 320 + hw];
    float mk = mask [((long long)b * 144 + g * 9 + kk) * 320 + hw];

    float py = dy + (float)(ky + h - 1);
    float px = dx + (float)(kx + w - 1);
    float y0f = floorf(py), x0f = floorf(px);
    int   y0 = (int)y0f,   x0 = (int)x0f;
    float ly = py - y0f,   lx = px - x0f;

    const float* Xp = g_Xg + ((long long)(b * Gg + g) * Hh * Ww) * Cg;
    bool yin0 = (y0 >= 0)     && (y0 < Hh);
    bool yin1 = (y0 + 1 >= 0) && (y0 + 1 < Hh);
    bool xin0 = (x0 >= 0)     && (x0 < Ww);
    bool xin1 = (x0 + 1 >= 0) && (x0 + 1 < Ww);

    float v00 = (yin0 && xin0) ? Xp[((y0    ) * Ww + x0    ) * Cg + lane] : 0.f;
    float v01 = (yin0 && xin1) ? Xp[((y0    ) * Ww + x0 + 1) * Cg + lane] : 0.f;
    float v10 = (yin1 && xin0) ? Xp[((y0 + 1) * Ww + x0    ) * Cg + lane] : 0.f;
    float v11 = (yin1 && xin1) ? Xp[((y0 + 1) * Ww + x0 + 1) * Cg + lane] : 0.f;

    float val = (1.f - ly) * (1.f - lx) * v00
              + (1.f - ly) * lx         * v01
              + ly         * (1.f - lx) * v10
              + ly         * lx         * v11;
    val *= mk;

    int m = (b * Hh + h) * Ww + w;
    g_col[(long long)m * Kd + g * (KKn * Cg) + kk * Cg + lane] = val;
}

// ---------------- 5) fp32 SIMT GEMM: out = col @ Bt + bias ------------------
// M=10240, N=512, K=4608; 128x128 block tile, 16 k-tile, 8x8 per thread.
#define GM_BM 128
#define GM_BN 128
#define GM_BK 16

__global__ __launch_bounds__(256) void gemm_kernel(const float* __restrict__ bias,
                                                   float* __restrict__ out) {
    __shared__ float As[GM_BK][GM_BM + 4];   // stored transposed: As[k][m]
    __shared__ float Bs[GM_BK][GM_BN];       // Bs[k][n]

    const int tid = threadIdx.x;
    const int m0 = blockIdx.x * GM_BM;
    const int n0 = blockIdx.y * GM_BN;
    const int ty = tid >> 4;   // 0..15
    const int tx = tid & 15;   // 0..15

    float acc[8][8];
#pragma unroll
    for (int i = 0; i < 8; i++)
#pragma unroll
        for (int j = 0; j < 8; j++) acc[i][j] = 0.f;

    for (int k0 = 0; k0 < Kd; k0 += GM_BK) {
        // load A tile (128 x 16) -> transposed into As[k][m]
#pragma unroll
        for (int l = 0; l < 2; l++) {
            int v   = tid + l * 256;          // 0..511
            int row = v >> 2;                 // 0..127
            int cv  = v & 3;                  // float4 index along k
            float4 a = *(const float4*)(g_col + (long long)(m0 + row) * Kd + k0 + cv * 4);
            As[cv * 4 + 0][row] = a.x;
            As[cv * 4 + 1][row] = a.y;
            As[cv * 4 + 2][row] = a.z;
            As[cv * 4 + 3][row] = a.w;
        }
        // load B tile (16 x 128)
#pragma unroll
        for (int l = 0; l < 2; l++) {
            int v   = tid + l * 256;
            int kr  = v >> 5;                 // 0..15
            int ncv = v & 31;                 // float4 index along n
            *(float4*)&Bs[kr][ncv * 4] =
                *(const float4*)(g_Bt + (long long)(k0 + kr) * Nn + n0 + ncv * 4);
        }
        __syncthreads();

#pragma unroll
        for (int kk = 0; kk < GM_BK; kk++) {
            float ar[8], br[8];
            *(float4*)(ar)     = *(const float4*)&As[kk][ty * 8];
            *(float4*)(ar + 4) = *(const float4*)&As[kk][ty * 8 + 4];
            *(float4*)(br)     = *(const float4*)&Bs[kk][tx * 8];
            *(float4*)(br + 4) = *(const float4*)&Bs[kk][tx * 8 + 4];
#pragma unroll
            for (int i = 0; i < 8; i++)
#pragma unroll
                for (int j = 0; j < 8; j++)
                    acc[i][j] = fmaf(ar[i], br[j], acc[i][j]);
        }
        __syncthreads();
    }

    // epilogue: out[(bflat*512 + o)*32 + t], m = bflat*32 + t
#pragma unroll
    for (int i = 0; i < 8; i++) {
        int m = m0 + ty * 8 + i;
        int bflat = m >> 5;
        int t = m & 31;
#pragma unroll
        for (int j = 0; j < 8; j++) {
            int o = n0 + tx * 8 + j;
            out[((long long)bflat * Nn + o) * Tt + t] = acc[i][j] + bias[o];
        }
    }
}

// ---------------- launch ----------------------------------------------------
extern "C" void kernel_launch(void* const* d_in, const int* in_sizes, int n_in,
                              void* d_out, int out_size) {
    const float* x      = (const float*)d_in[0];
    const float* offset = (const float*)d_in[1];
    const float* mask   = (const float*)d_in[2];
    const float* gamma  = (const float*)d_in[3];
    const float* beta   = (const float*)d_in[4];
    const float* weight = (const float*)d_in[5];
    const float* bias   = (const float*)d_in[6];
    float* out = (float*)d_out;

    bn_stats_kernel<<<Cc, 256>>>(x);

    {
        int n = BSz * Gg * Hh * Ww * Cg;
        build_xg_kernel<<<(n + 255) / 256, 256>>>(x, gamma, beta);
    }
    {
        int n = Kd * Nn;
        wtrans_kernel<<<(n + 255) / 256, 256>>>(weight);
    }
    {
        int warps = BSz * Gg * Hh * Ww * KKn;     // 1,474,560
        int threads = warps * 32;
        im2col_kernel<<<(threads + 255) / 256, 256>>>(offset, mask);
    }
    {
        dim3 grid(Mm / GM_BM, Nn / GM_BN);        // (80, 4)
        gemm_kernel<<<grid, 256>>>(bias, out);
    }
}

// round 2
// speedup vs baseline: 1.0044x; 1.0044x over previous
#include <cuda_runtime.h>

// ---------------- problem constants (fixed shapes from setup_inputs) --------
#define Bb   320      // x batch
#define Cc   512      // channels
#define Tt   32       // time (== W)
#define BSz  32       // deform batch (Bb/10)
#define Hh   10
#define Ww   32
#define Gg   16       // groups
#define Cg   32       // channels per group
#define KKn  9        // 3x3 taps
#define Kd   4608     // Gg*KKn*Cg  (GEMM reduction dim)
#define Mm   10240    // BSz*Hh*Ww  (GEMM rows)
#define Nn   512      // output channels (GEMM cols)

// ---------------- device scratch (no allocations allowed) -------------------
__device__ float g_mean[Cc];
__device__ float g_istd[Cc];
__device__ float g_Xg[BSz * Gg * Hh * Ww * Cg];      // normalized, group-major, c contiguous
__device__ float g_col[(long long)Mm * Kd];          // im2col of deformable samples (189 MB)
__device__ float g_Bt[(long long)Kd * Nn];           // weight permuted to [kd][o]

// ---------------- 1) BN statistics per channel ------------------------------
__global__ void bn_stats_kernel(const float* __restrict__ x) {
    int c = blockIdx.x;
    float s = 0.f, s2 = 0.f;
    for (int i = threadIdx.x; i < Bb * Tt; i += blockDim.x) {
        int b = i >> 5;       // Tt == 32
        int t = i & 31;
        float v = x[(b * Cc + c) * Tt + t];
        s += v; s2 += v * v;
    }
    __shared__ float sh[256], sh2[256];
    sh[threadIdx.x] = s; sh2[threadIdx.x] = s2;
    __syncthreads();
    for (int o = 128; o > 0; o >>= 1) {
        if (threadIdx.x < o) {
            sh[threadIdx.x]  += sh[threadIdx.x + o];
            sh2[threadIdx.x] += sh2[threadIdx.x + o];
        }
        __syncthreads();
    }
    if (threadIdx.x == 0) {
        const float inv_n = 1.0f / (float)(Bb * Tt);
        float mean = sh[0] * inv_n;
        float var  = sh2[0] * inv_n - mean * mean;
        g_mean[c] = mean;
        g_istd[c] = rsqrtf(var + 1e-5f);
    }
}

// ---------------- 2) normalize + relayout to (bs,g,h,w,c) -------------------
__global__ void build_xg_kernel(const float* __restrict__ x,
                                const float* __restrict__ gamma,
                                const float* __restrict__ beta) {
    int idx = blockIdx.x * blockDim.x + threadIdx.x;
    if (idx >= BSz * Gg * Hh * Ww * Cg) return;
    int c  = idx & 31;
    int w  = (idx >> 5) & 31;
    int h  = (idx >> 10) % Hh;
    int g  = (idx / (Cg * Ww * Hh)) % Gg;
    int bs = idx / (Cg * Ww * Hh * Gg);
    int ch = g * Cg + c;
    float v = x[((bs * 10 + h) * Cc + ch) * Tt + w];
    g_Xg[idx] = (v - g_mean[ch]) * g_istd[ch] * gamma[ch] + beta[ch];
}

// ---------------- 3) permute weight to [kd][o] ------------------------------
__global__ void wtrans_kernel(const float* __restrict__ weight) {
    int idx = blockIdx.x * blockDim.x + threadIdx.x;
    if (idx >= Kd * Nn) return;
    int o  = idx & (Nn - 1);
    int kd = idx >> 9;
    int g  = kd / (KKn * Cg);
    int r  = kd % (KKn * Cg);
    int kk = r >> 5;
    int c  = r & 31;
    g_Bt[(long long)kd * Nn + o] = weight[(long long)o * Kd + (g * Cg + c) * KKn + kk];
}

// ---------------- 4) deformable bilinear sampling -> col --------------------
// One warp handles one (b,g,h,w,kk); lane == channel within group.
__global__ void im2col_kernel(const float* __restrict__ offset,
                              const float* __restrict__ mask) {
    int warp = (blockIdx.x * blockDim.x + threadIdx.x) >> 5;
    int lane = threadIdx.x & 31;
    if (warp >= BSz * Gg * Hh * Ww * KKn) return;

    int kk = warp % 9;
    int w  = (warp / 9) % 32;
    int h  = (warp / 288) % 10;
    int g  = (warp / 2880) % 16;
    int b  = warp / 46080;

    int ky = kk / 3, kx = kk % 3;
    int hw = h * Ww + w;

    // offset channel layout: (g*9+kk)*2 + {0:dy,1:dx}; plane stride H*W = 320
    int oc = (g * 9 + kk) * 2;
    float dy = offset[((long long)b * 288 + oc)     * 320 + hw];
    float dx = offset[((long long)b * 288 + oc + 1) * 320 + hw];
    float mk = mask [((long long)b * 144 + g * 9 + kk) * 320 + hw];

    float py = dy + (float)(ky + h - 1);
    float px = dx + (float)(kx + w - 1);
    float y0f = floorf(py), x0f = floorf(px);
    int   y0 = (int)y0f,   x0 = (int)x0f;
    float ly = py - y0f,   lx = px - x0f;

    const float* Xp = g_Xg + ((long long)(b * Gg + g) * Hh * Ww) * Cg;
    bool yin0 = (y0 >= 0)     && (y0 < Hh);
    bool yin1 = (y0 + 1 >= 0) && (y0 + 1 < Hh);
    bool xin0 = (x0 >= 0)     && (x0 < Ww);
    bool xin1 = (x0 + 1 >= 0) && (x0 + 1 < Ww);

    float v00 = (yin0 && xin0) ? Xp[((y0    ) * Ww + x0    ) * Cg + lane] : 0.f;
    float v01 = (yin0 && xin1) ? Xp[((y0    ) * Ww + x0 + 1) * Cg + lane] : 0.f;
    float v10 = (yin1 && xin0) ? Xp[((y0 + 1) * Ww + x0    ) * Cg + lane] : 0.f;
    float v11 = (yin1 && xin1) ? Xp[((y0 + 1) * Ww + x0 + 1) * Cg + lane] : 0.f;

    float val = (1.f - ly) * (1.f - lx) * v00
              + (1.f - ly) * lx         * v01
              + ly         * (1.f - lx) * v10
              + ly         * lx         * v11;
    val *= mk;

    int m = (b * Hh + h) * Ww + w;
    g_col[(long long)m * Kd + g * (KKn * Cg) + kk * Cg + lane] = val;
}

// ---------------- 5) fp32 SIMT GEMM: out = col @ Bt + bias ------------------
// M=10240, N=512, K=4608; 128x128 block tile, 16 k-tile, 8x8 per thread.
#define GM_BM 128
#define GM_BN 128
#define GM_BK 16

__global__ __launch_bounds__(256) void gemm_kernel(const float* __restrict__ bias,
                                                   float* __restrict__ out) {
    __shared__ float As[GM_BK][GM_BM + 4];   // stored transposed: As[k][m]
    __shared__ float Bs[GM_BK][GM_BN];       // Bs[k][n]

    const int tid = threadIdx.x;
    const int m0 = blockIdx.x * GM_BM;
    const int n0 = blockIdx.y * GM_BN;
    const int ty = tid >> 4;   // 0..15
    const int tx = tid & 15;   // 0..15

    float acc[8][8];
#pragma unroll
    for (int i = 0; i < 8; i++)
#pragma unroll
        for (int j = 0; j < 8; j++) acc[i][j] = 0.f;

    for (int k0 = 0; k0 < Kd; k0 += GM_BK) {
        // load A tile (128 x 16) -> transposed into As[k][m]
#pragma unroll
        for (int l = 0; l < 2; l++) {
            int v   = tid + l * 256;          // 0..511
            int row = v >> 2;                 // 0..127
            int cv  = v & 3;                  // float4 index along k
            float4 a = *(const float4*)(g_col + (long long)(m0 + row) * Kd + k0 + cv * 4);
            As[cv * 4 + 0][row] = a.x;
            As[cv * 4 + 1][row] = a.y;
            As[cv * 4 + 2][row] = a.z;
            As[cv * 4 + 3][row] = a.w;
        }
        // load B tile (16 x 128)
#pragma unroll
        for (int l = 0; l < 2; l++) {
            int v   = tid + l * 256;
            int kr  = v >> 5;                 // 0..15
            int ncv = v & 31;                 // float4 index along n
            *(float4*)&Bs[kr][ncv * 4] =
                *(const float4*)(g_Bt + (long long)(k0 + kr) * Nn + n0 + ncv * 4);
        }
        __syncthreads();

#pragma unroll
        for (int kk = 0; kk < GM_BK; kk++) {
            float ar[8], br[8];
            *(float4*)(ar)     = *(const float4*)&As[kk][ty * 8];
            *(float4*)(ar + 4) = *(const float4*)&As[kk][ty * 8 + 4];
            *(float4*)(br)     = *(const float4*)&Bs[kk][tx * 8];
            *(float4*)(br + 4) = *(const float4*)&Bs[kk][tx * 8 + 4];
#pragma unroll
            for (int i = 0; i < 8; i++)
#pragma unroll
                for (int j = 0; j < 8; j++)
                    acc[i][j] = fmaf(ar[i], br[j], acc[i][j]);
        }
        __syncthreads();
    }

    // epilogue: out[(bflat*512 + o)*32 + t], m = bflat*32 + t
#pragma unroll
    for (int i = 0; i < 8; i++) {
        int m = m0 + ty * 8 + i;
        int bflat = m >> 5;
        int t = m & 31;
#pragma unroll
        for (int j = 0; j < 8; j++) {
            int o = n0 + tx * 8 + j;
            out[((long long)bflat * Nn + o) * Tt + t] = acc[i][j] + bias[o];
        }
    }
}

// ---------------- launch ----------------------------------------------------
extern "C" void kernel_launch(void* const* d_in, const int* in_sizes, int n_in,
                              void* d_out, int out_size) {
    const float* x      = (const float*)d_in[0];
    const float* offset = (const float*)d_in[1];
    const float* mask   = (const float*)d_in[2];
    const float* gamma  = (const float*)d_in[3];
    const float* beta   = (const float*)d_in[4];
    const float* weight = (const float*)d_in[5];
    const float* bias   = (const float*)d_in[6];
    float* out = (float*)d_out;

    bn_stats_kernel<<<Cc, 256>>>(x);

    {
        int n = BSz * Gg * Hh * Ww * Cg;
        build_xg_kernel<<<(n + 255) / 256, 256>>>(x, gamma, beta);
    }
    {
        int n = Kd * Nn;
        wtrans_kernel<<<(n + 255) / 256, 256>>>(weight);
    }
    {
        int warps = BSz * Gg * Hh * Ww * KKn;     // 1,474,560
        int threads = warps * 32;
        im2col_kernel<<<(threads + 255) / 256, 256>>>(offset, mask);
    }
    {
        dim3 grid(Mm / GM_BM, Nn / GM_BN);        // (80, 4)
        gemm_kernel<<<grid, 256>>>(bias, out);
    }
}

// round 5
// speedup vs baseline: 2.4764x; 2.4656x over previous
#include <cuda_runtime.h>
#include <cstdint>

// ---------------- problem constants (fixed shapes) --------------------------
#define Bb   320
#define Cc   512
#define Tt   32
#define BSz  32
#define Hh   10
#define Ww   32
#define Gg   16
#define Cg   32
#define KKn  9
#define Kd   4608      // Gg*KKn*Cg
#define Mm   10240     // BSz*Hh*Ww
#define Nn   512

// ---------------- device scratch --------------------------------------------
__device__ float g_mean[Cc];
__device__ float g_istd[Cc];
__device__ __align__(128) float g_Xg[BSz * Gg * Hh * Ww * Cg];
__device__ __align__(128) float g_col[(size_t)Mm * Kd];   // 189 MB, tf32-rounded
__device__ __align__(128) float g_Bt[(size_t)Kd * Nn];    // 9.4 MB, [kd][o], tf32-rounded

// ---------------- helpers ----------------------------------------------------
__device__ __forceinline__ float tf32r(float x) {
    uint32_t r;
    asm("cvt.rna.tf32.f32 %0, %1;" : "=r"(r) : "f"(x));
    return __uint_as_float(r);
}
__device__ __forceinline__ uint32_t smem_u32(const void* p) {
    uint32_t a;
    asm("{ .reg .u64 t; cvta.to.shared.u64 t, %1; cvt.u32.u64 %0, t; }" : "=r"(a) : "l"(p));
    return a;
}
__device__ __forceinline__ void cp_async16(uint32_t dst, const void* src) {
    asm volatile("cp.async.cg.shared.global [%0], [%1], 16;" :: "r"(dst), "l"(src) : "memory");
}
#define CP_COMMIT() asm volatile("cp.async.commit_group;" ::: "memory")
#define CP_WAIT2()  asm volatile("cp.async.wait_group 2;" ::: "memory")

__device__ __forceinline__ void mma_tf32(float* c, const float* a, const float* b) {
    asm volatile(
        "mma.sync.aligned.m16n8k8.row.col.f32.tf32.tf32.f32 "
        "{%0,%1,%2,%3}, {%4,%5,%6,%7}, {%8,%9}, {%0,%1,%2,%3};"
        : "+f"(c[0]), "+f"(c[1]), "+f"(c[2]), "+f"(c[3])
        : "r"(__float_as_uint(a[0])), "r"(__float_as_uint(a[1])),
          "r"(__float_as_uint(a[2])), "r"(__float_as_uint(a[3])),
          "r"(__float_as_uint(b[0])), "r"(__float_as_uint(b[1])));
}

// ---------------- 1) BN statistics ------------------------------------------
__global__ void bn_stats_kernel(const float* __restrict__ x) {
    int c = blockIdx.x;
    float s = 0.f, s2 = 0.f;
    for (int i = threadIdx.x; i < Bb * Tt; i += blockDim.x) {
        int b = i >> 5, t = i & 31;
        float v = x[(b * Cc + c) * Tt + t];
        s += v; s2 += v * v;
    }
    __shared__ float sh[256], sh2[256];
    sh[threadIdx.x] = s; sh2[threadIdx.x] = s2;
    __syncthreads();
    for (int o = 128; o > 0; o >>= 1) {
        if (threadIdx.x < o) {
            sh[threadIdx.x]  += sh[threadIdx.x + o];
            sh2[threadIdx.x] += sh2[threadIdx.x + o];
        }
        __syncthreads();
    }
    if (threadIdx.x == 0) {
        const float inv_n = 1.0f / (float)(Bb * Tt);
        float mean = sh[0] * inv_n;
        float var  = sh2[0] * inv_n - mean * mean;
        g_mean[c] = mean;
        g_istd[c] = rsqrtf(var + 1e-5f);
    }
}

// ---------------- 2) normalize + relayout to (bs,g,h,w,c) -------------------
__global__ void build_xg_kernel(const float* __restrict__ x,
                                const float* __restrict__ gamma,
                                const float* __restrict__ beta) {
    int idx = blockIdx.x * blockDim.x + threadIdx.x;
    if (idx >= BSz * Gg * Hh * Ww * Cg) return;
    int c  = idx & 31;
    int w  = (idx >> 5) & 31;
    int h  = (idx >> 10) % Hh;
    int g  = (idx / (Cg * Ww * Hh)) % Gg;
    int bs = idx / (Cg * Ww * Hh * Gg);
    int ch = g * Cg + c;
    float v = x[((bs * 10 + h) * Cc + ch) * Tt + w];
    g_Xg[idx] = (v - g_mean[ch]) * g_istd[ch] * gamma[ch] + beta[ch];
}

// ---------------- 3) weight -> tf32, [kd][o] layout -------------------------
__global__ void wtrans_kernel(const float* __restrict__ weight) {
    int kd = blockIdx.x * 256 + threadIdx.x;
    if (kd >= Kd) return;
    int o  = blockIdx.y;
    int g  = kd / (KKn * Cg);
    int r  = kd % (KKn * Cg);
    int kk = r >> 5;
    int c  = r & 31;
    g_Bt[(size_t)kd * Nn + o] = tf32r(weight[(size_t)o * Kd + (g * Cg + c) * KKn + kk]);
}

// ---------------- 4) deformable sampling -> tf32 col ------------------------
// grid (Ww, Hh, BSz*Gg), block 288 = 9 warps; warp = tap, lane = channel.
__global__ __launch_bounds__(288) void im2col_kernel(const float* __restrict__ offset,
                                                     const float* __restrict__ mask) {
    int w  = blockIdx.x, h = blockIdx.y;
    int b  = blockIdx.z >> 4;
    int g  = blockIdx.z & 15;
    int kk = threadIdx.x >> 5;
    int lane = threadIdx.x & 31;

    int ky = kk / 3, kx = kk % 3;
    int hw = h * Ww + w;

    int oc = (g * 9 + kk) * 2;
    float dy = offset[((size_t)b * 288 + oc)     * 320 + hw];
    float dx = offset[((size_t)b * 288 + oc + 1) * 320 + hw];
    float mk = mask [((size_t)b * 144 + g * 9 + kk) * 320 + hw];

    float py = dy + (float)(ky + h - 1);
    float px = dx + (float)(kx + w - 1);
    float y0f = floorf(py), x0f = floorf(px);
    int   y0 = (int)y0f,   x0 = (int)x0f;
    float ly = py - y0f,   lx = px - x0f;

    const float* Xp = g_Xg + ((size_t)(b * Gg + g) * Hh * Ww) * Cg;
    bool yin0 = (y0 >= 0)     && (y0 < Hh);
    bool yin1 = (y0 + 1 >= 0) && (y0 + 1 < Hh);
    bool xin0 = (x0 >= 0)     && (x0 < Ww);
    bool xin1 = (x0 + 1 >= 0) && (x0 + 1 < Ww);

    float v00 = (yin0 && xin0) ? Xp[((y0    ) * Ww + x0    ) * Cg + lane] : 0.f;
    float v01 = (yin0 && xin1) ? Xp[((y0    ) * Ww + x0 + 1) * Cg + lane] : 0.f;
    float v10 = (yin1 && xin0) ? Xp[((y0 + 1) * Ww + x0    ) * Cg + lane] : 0.f;
    float v11 = (yin1 && xin1) ? Xp[((y0 + 1) * Ww + x0 + 1) * Cg + lane] : 0.f;

    float val = (1.f - ly) * (1.f - lx) * v00
              + (1.f - ly) * lx         * v01
              + ly         * (1.f - lx) * v10
              + ly         * lx         * v11;
    val *= mk;

    int m = (b * Hh + h) * Ww + w;
    g_col[(size_t)m * Kd + g * (KKn * Cg) + kk * Cg + lane] = tf32r(val);
}

// ---------------- 5) TF32 mma.sync GEMM -------------------------------------
// CTA 128x128, BK=32, 3-stage cp.async pipeline, 8 warps (2x4), warp 64x32.
#define BM 128
#define BN 128
#define BK 32
#define AST 36                 // A smem row stride (floats)
#define BST 132                // B smem row stride (floats)
#define ASZ (BM * AST)         // 4608 floats
#define BSZ (BK * BST)         // 4224 floats
#define STAGE_F (ASZ + BSZ)    // 8832 floats = 35328 B
#define NSTG 144               // Kd / BK
#define GSMEM (3 * STAGE_F * 4)

__device__ __forceinline__ void load_stage(float* sm, int s, int tid, int m0, int n0) {
    float* dst = sm + (s % 3) * STAGE_F;
    int k0 = s * BK;
#pragma unroll
    for (int i = 0; i < 4; i++) {
        int q   = tid + (i << 8);
        int row = q >> 3;
        int kc  = (q & 7) << 2;
        cp_async16(smem_u32(dst + row * AST + kc),
                   g_col + (size_t)(m0 + row) * Kd + k0 + kc);
    }
    float* bdst = dst + ASZ;
#pragma unroll
    for (int i = 0; i < 4; i++) {
        int q   = tid + (i << 8);
        int row = q >> 5;
        int nc  = (q & 31) << 2;
        cp_async16(smem_u32(bdst + row * BST + nc),
                   g_Bt + (size_t)(k0 + row) * Nn + n0 + nc);
    }
}

__global__ __launch_bounds__(256, 2) void gemm_kernel(const float* __restrict__ bias,
                                                      float* __restrict__ out) {
    extern __shared__ float sm[];
    const int tid  = threadIdx.x;
    const int wid  = tid >> 5;
    const int lane = tid & 31;
    const int gID  = lane >> 2;       // 0..7
    const int tg   = lane & 3;        // 0..3
    const int wm   = wid & 1;         // m offset 64*wm
    const int wn   = wid >> 1;        // n offset 32*wn
    const int n0   = blockIdx.x * BN;
    const int m0   = blockIdx.y * BM;

    float acc[4][4][4];
#pragma unroll
    for (int i = 0; i < 4; i++)
#pragma unroll
        for (int j = 0; j < 4; j++)
#pragma unroll
            for (int k = 0; k < 4; k++) acc[i][j][k] = 0.f;

    load_stage(sm, 0, tid, m0, n0); CP_COMMIT();
    load_stage(sm, 1, tid, m0, n0); CP_COMMIT();
    load_stage(sm, 2, tid, m0, n0); CP_COMMIT();

    for (int s = 0; s < NSTG; s++) {
        CP_WAIT2();
        __syncthreads();

        const float* As = sm + (s % 3) * STAGE_F;
        const float* Bs = As + ASZ;
        const float* Aw = As + (wm * 64 + gID) * AST + tg;
        const float* Bw = Bs + tg * BST + wn * 32 + gID;

#pragma unroll
        for (int ks = 0; ks < 4; ks++) {
            int kk = ks << 3;
            float a[4][4];
#pragma unroll
            for (int mt = 0; mt < 4; mt++) {
                const float* ap = Aw + (mt * 16) * AST + kk;
                a[mt][0] = ap[0];
                a[mt][1] = ap[8 * AST];
                a[mt][2] = ap[4];
                a[mt][3] = ap[8 * AST + 4];
            }
            float b[4][2];
#pragma unroll
            for (int nt = 0; nt < 4; nt++) {
                const float* bp = Bw + kk * BST + nt * 8;
                b[nt][0] = bp[0];
                b[nt][1] = bp[4 * BST];
            }
#pragma unroll
            for (int mt = 0; mt < 4; mt++)
#pragma unroll
                for (int nt = 0; nt < 4; nt++)
                    mma_tf32(acc[mt][nt], a[mt], b[nt]);
        }

        __syncthreads();
        if (s + 3 < NSTG) load_stage(sm, s + 3, tid, m0, n0);
        CP_COMMIT();
    }

    // epilogue: out[(m>>5)*Nn*Tt + o*Tt + (m&31)] = acc + bias[o]
#pragma unroll
    for (int nt = 0; nt < 4; nt++) {
        int o0 = n0 + wn * 32 + nt * 8 + 2 * tg;
        float bi0 = __ldg(&bias[o0]);
        float bi1 = __ldg(&bias[o0 + 1]);
#pragma unroll
        for (int mt = 0; mt < 4; mt++) {
            int r = m0 + wm * 64 + mt * 16 + gID;
#pragma unroll
            for (int half = 0; half < 2; half++) {
                int m = r + half * 8;
                size_t base = ((size_t)(m >> 5) * Nn) * Tt + (m & 31);
                out[base + (size_t)o0 * Tt]       = acc[mt][nt][half * 2]     + bi0;
                out[base + (size_t)(o0 + 1) * Tt] = acc[mt][nt][half * 2 + 1] + bi1;
            }
        }
    }
}

// ---------------- launch ----------------------------------------------------
static bool g_attr_set = false;

extern "C" void kernel_launch(void* const* d_in, const int* in_sizes, int n_in,
                              void* d_out, int out_size) {
    const float* x      = (const float*)d_in[0];
    const float* offset = (const float*)d_in[1];
    const float* mask   = (const float*)d_in[2];
    const float* gamma  = (const float*)d_in[3];
    const float* beta   = (const float*)d_in[4];
    const float* weight = (const float*)d_in[5];
    const float* bias   = (const float*)d_in[6];
    float* out = (float*)d_out;

    if (!g_attr_set) {
        cudaFuncSetAttribute(gemm_kernel, cudaFuncAttributeMaxDynamicSharedMemorySize, GSMEM);
        g_attr_set = true;
    }

    bn_stats_kernel<<<Cc, 256>>>(x);
    {
        int n = BSz * Gg * Hh * Ww * Cg;
        build_xg_kernel<<<(n + 255) / 256, 256>>>(x, gamma, beta);
    }
    wtrans_kernel<<<dim3((Kd + 255) / 256, Nn), 256>>>(weight);
    im2col_kernel<<<dim3(Ww, Hh, BSz * Gg), 288>>>(offset, mask);

    gemm_kernel<<<dim3(Nn / BN, Mm / BM), 256, GSMEM>>>(bias, out);
}